// round 6
// baseline (speedup 1.0000x reference)
#include <cuda_runtime.h>
#include <cstdint>

#define NN 32768
#define KK 8192
#define DD 512

// ---------------- device scratch (no allocations allowed) ----------------
__device__ float  g_sz[NN];      // fl32( sum_d z[n,d]^2 )  (correctly rounded via double)
__device__ float  g_se[KK];      // fl32( sum_d e[k,d]^2 )
__device__ int    g_idx[NN];     // argmin indices
__device__ double g_losssum;     // sum of fl32((q-z)^2)

// ---------------- init (graph replays must be deterministic) --------------
__global__ void vq_init()
{
    g_losssum = 0.0;
}

// ---------------- row squared-norms: one warp per row ---------------------
// which==0 -> g_sz (rows=NN), which==1 -> g_se (rows=KK)
__global__ void vq_rowsq(const float* __restrict__ x, int rows, int which)
{
    int row  = blockIdx.x * 8 + (threadIdx.x >> 5);
    int lane = threadIdx.x & 31;
    if (row >= rows) return;
    const float4* xr = (const float4*)(x + (size_t)row * DD);
    double s = 0.0;
    #pragma unroll
    for (int i = 0; i < 4; i++) {
        float4 v = xr[lane + 32 * i];
        s += (double)v.x * v.x + (double)v.y * v.y
           + (double)v.z * v.z + (double)v.w * v.w;
    }
    #pragma unroll
    for (int o = 16; o >= 1; o >>= 1)
        s += __shfl_down_sync(0xffffffffu, s, o);
    if (lane == 0) {
        float r = (float)s;
        if (which == 0) g_sz[row] = r; else g_se[row] = r;
    }
}

// ---------------- fused GEMM + argmin -------------------------------------
// Block: 256 threads, tile BM=128 rows x BN=64 codebook entries, loops all K.
// Per thread: TM=8 x TN=4 accumulators. Distances are computed with the
// reference's fp32 rounding: dist = fl( fl(sz + se_k) - fl(2*dot) ).
// dot accumulation: single fp32 FMA chain, strictly ascending d (matches
// the reference GEMM's sequential-k accumulation order as closely as possible).
// Tie-break: strict '<' keeps the earliest k within a thread (ks ascend),
// cross-lane reduce prefers lower index on exact float equality.
__global__ void __launch_bounds__(256, 2)
vq_gemm_argmin(const float* __restrict__ z, const float* __restrict__ e)
{
    __shared__ float As[16][128];   // [d][row]  8 KB
    __shared__ float Bs[16][64];    // [d][k]    4 KB

    const int tid = threadIdx.x;
    const int tx  = tid & 15;       // codebook column group (TN=4)
    const int ty  = tid >> 4;       // row group (TM=8)
    const int m0  = blockIdx.x * 128;

    const int zr0    = tid >> 2;          // 0..63
    const int zr1    = zr0 + 64;          // 64..127
    const int er     = tid >> 2;          // 0..63
    const int dgBase = (tid & 3) * 4;     // depth sub-offset (floats)

    const float* zp0 = z + (size_t)(m0 + zr0) * DD + dgBase;
    const float* zp1 = z + (size_t)(m0 + zr1) * DD + dgBase;

    float S[8];
    #pragma unroll
    for (int i = 0; i < 8; i++) S[i] = g_sz[m0 + ty * 8 + i];

    float bestd[8];
    int   bestk[8];
    #pragma unroll
    for (int i = 0; i < 8; i++) { bestd[i] = 3.4e38f; bestk[i] = 0; }

    #pragma unroll 1
    for (int kt = 0; kt < KK; kt += 64) {
        const float* ep = e + (size_t)(kt + er) * DD + dgBase;

        float acc[8][4];
        #pragma unroll
        for (int i = 0; i < 8; i++)
            #pragma unroll
            for (int j = 0; j < 4; j++) acc[i][j] = 0.0f;

        float4 za0 = *(const float4*)zp0;
        float4 za1 = *(const float4*)zp1;
        float4 eb  = *(const float4*)ep;

        #pragma unroll 1
        for (int d0 = 0; d0 < DD; d0 += 16) {
            __syncthreads();
            As[dgBase + 0][zr0] = za0.x; As[dgBase + 1][zr0] = za0.y;
            As[dgBase + 2][zr0] = za0.z; As[dgBase + 3][zr0] = za0.w;
            As[dgBase + 0][zr1] = za1.x; As[dgBase + 1][zr1] = za1.y;
            As[dgBase + 2][zr1] = za1.z; As[dgBase + 3][zr1] = za1.w;
            Bs[dgBase + 0][er]  = eb.x;  Bs[dgBase + 1][er]  = eb.y;
            Bs[dgBase + 2][er]  = eb.z;  Bs[dgBase + 3][er]  = eb.w;
            __syncthreads();

            if (d0 + 16 < DD) {               // software-pipeline next tile
                za0 = *(const float4*)(zp0 + d0 + 16);
                za1 = *(const float4*)(zp1 + d0 + 16);
                eb  = *(const float4*)(ep  + d0 + 16);
            }

            #pragma unroll
            for (int dd = 0; dd < 16; dd++) {
                float a[8], b[4];
                *(float4*)&a[0] = *(const float4*)&As[dd][ty * 8];
                *(float4*)&a[4] = *(const float4*)&As[dd][ty * 8 + 4];
                *(float4*)&b[0] = *(const float4*)&Bs[dd][tx * 4];
                #pragma unroll
                for (int i = 0; i < 8; i++)
                    #pragma unroll
                    for (int j = 0; j < 4; j++)
                        acc[i][j] = fmaf(a[i], b[j], acc[i][j]);
            }
        }

        // epilogue: distance + running argmin (k ascending within thread)
        #pragma unroll
        for (int j = 0; j < 4; j++) {
            int   kk  = kt + tx * 4 + j;
            float seK = g_se[kk];
            #pragma unroll
            for (int i = 0; i < 8; i++) {
                float A    = S[i] + seK;          // fl(sz + se_k)
                float dist = A - 2.0f * acc[i][j];// fl(A - 2*dot) (2*dot exact)
                if (dist < bestd[i]) { bestd[i] = dist; bestk[i] = kk; }
            }
        }
    }

    // reduce across the 16 tx lanes (lowest index wins on exact ties)
    #pragma unroll
    for (int o = 8; o >= 1; o >>= 1) {
        #pragma unroll
        for (int i = 0; i < 8; i++) {
            float od = __shfl_xor_sync(0xffffffffu, bestd[i], o);
            int   ok = __shfl_xor_sync(0xffffffffu, bestk[i], o);
            if (od < bestd[i] || (od == bestd[i] && ok < bestk[i])) {
                bestd[i] = od; bestk[i] = ok;
            }
        }
    }
    if (tx == 0) {
        #pragma unroll
        for (int i = 0; i < 8; i++) g_idx[m0 + ty * 8 + i] = bestk[i];
    }
}

// ---------------- gather + straight-through + loss sum --------------------
// out[row,d] = fl( z + fl(q - z) )   (reference STE rounding, NOT just q)
// loss accumulates fl32((q-z)^2) in double.
__global__ void vq_gather(const float* __restrict__ z, const float* __restrict__ e,
                          float* __restrict__ out, int write_q)
{
    __shared__ double warpsum[4];
    int row = blockIdx.x;
    int t   = threadIdx.x;                    // 0..127, one float4 each
    int k   = g_idx[row];
    float4 q  = ((const float4*)(e + (size_t)k   * DD))[t];
    float4 zz = ((const float4*)(z + (size_t)row * DD))[t];
    float d0 = q.x - zz.x, d1 = q.y - zz.y, d2 = q.z - zz.z, d3 = q.w - zz.w;
    if (write_q) {
        float4 o = make_float4(zz.x + d0, zz.y + d1, zz.z + d2, zz.w + d3);
        ((float4*)out)[(size_t)row * (DD / 4) + t] = o;
    }
    float s0 = d0 * d0, s1 = d1 * d1, s2 = d2 * d2, s3 = d3 * d3; // square in f32
    double s = (double)s0 + (double)s1 + (double)s2 + (double)s3;
    #pragma unroll
    for (int o = 16; o >= 1; o >>= 1)
        s += __shfl_down_sync(0xffffffffu, s, o);
    if ((t & 31) == 0) warpsum[t >> 5] = s;
    __syncthreads();
    if (t == 0) {
        double tot = warpsum[0] + warpsum[1] + warpsum[2] + warpsum[3];
        atomicAdd(&g_losssum, tot);
    }
}

// ---------------- tail of output buffer: loss + indices (as float) --------
__global__ void vq_tail(float* __restrict__ out, long long out_size,
                        long long loss_pos, long long idx_base)
{
    long long pos = (long long)NN * DD + (long long)blockIdx.x * 256 + threadIdx.x;
    if (pos >= out_size) return;
    if (pos == loss_pos) {
        float m = (float)(g_losssum / (double)((long long)NN * DD));
        out[pos] = m + 0.25f * m;             // fl(m + fl(0.25*m)), 0.25*m exact
    } else if (idx_base >= 0 && pos >= idx_base && pos < idx_base + NN) {
        out[pos] = (float)g_idx[pos - idx_base];
    } else {
        out[pos] = 0.0f;
    }
}

__global__ void vq_idx_int(int* __restrict__ out)
{
    int i = blockIdx.x * 256 + threadIdx.x;
    if (i < NN) out[i] = g_idx[i];
}

__global__ void vq_loss_only(float* __restrict__ out)
{
    float m = (float)(g_losssum / (double)((long long)NN * DD));
    out[0] = m + 0.25f * m;
}

// ---------------- launch --------------------------------------------------
extern "C" void kernel_launch(void* const* d_in, const int* in_sizes, int n_in,
                              void* d_out, int out_size)
{
    const float* z = nullptr;
    const float* e = nullptr;
    for (int i = 0; i < n_in; i++) {
        if      (in_sizes[i] == NN * DD) z = (const float*)d_in[i];
        else if (in_sizes[i] == KK * DD) e = (const float*)d_in[i];
    }
    if (!z) z = (const float*)d_in[0];
    if (!e) e = (const float*)d_in[1];

    vq_init<<<1, 1>>>();
    vq_rowsq<<<NN / 8, 256>>>(z, NN, 0);
    vq_rowsq<<<KK / 8, 256>>>(e, KK, 1);
    vq_gemm_argmin<<<NN / 128, 256>>>(z, e);

    const long long QD = (long long)NN * DD;   // 16777216
    long long OS = (long long)out_size;

    if (OS >= QD) {
        vq_gather<<<NN, 128>>>(z, e, (float*)d_out, 1);
        long long rem = OS - QD;
        if (rem > 0) {
            long long loss_pos = -1, idx_base = -1;
            if (rem >= 1 + (long long)NN) { loss_pos = QD; idx_base = QD + 1; }
            else if (rem == (long long)NN) { idx_base = QD; }
            else { loss_pos = QD; }
            int blocks = (int)((rem + 255) / 256);
            vq_tail<<<blocks, 256>>>((float*)d_out, OS, loss_pos, idx_base);
        }
    } else if (OS == NN) {
        vq_gather<<<NN, 128>>>(z, e, nullptr, 0);
        vq_idx_int<<<NN / 256, 256>>>((int*)d_out);
    } else if (OS == 1) {
        vq_gather<<<NN, 128>>>(z, e, nullptr, 0);
        vq_loss_only<<<1, 1>>>((float*)d_out);
    } else {
        // unknown layout: still compute everything (deterministic work)
        vq_gather<<<NN, 128>>>(z, e, nullptr, 0);
    }
}

// round 9
// speedup vs baseline: 3.8535x; 3.8535x over previous
#include <cuda_runtime.h>
#include <cuda_bf16.h>
#include <cstdint>

#define NN 32768
#define KK 8192
#define DD 512
#define CAP (1 << 21)
#define EPS2 5e-4f   /* acc-domain threshold = (1e-3 distance margin) / 2 */

// ======================= PTX helpers (compute_103-safe) ===================
__device__ __forceinline__ uint32_t smem_to_u32(const void* p) {
    uint32_t a;
    asm("{ .reg .u64 t; cvta.to.shared.u64 t, %1; cvt.u32.u64 %0, t; }"
        : "=r"(a) : "l"(p));
    return a;
}
__device__ __forceinline__ void ldsm_x4(uint32_t* r, uint32_t addr) {
    asm volatile("ldmatrix.sync.aligned.m8n8.x4.shared.b16 {%0,%1,%2,%3}, [%4];"
        : "=r"(r[0]), "=r"(r[1]), "=r"(r[2]), "=r"(r[3]) : "r"(addr));
}
__device__ __forceinline__ void ldsm_x2(uint32_t* r, uint32_t addr) {
    asm volatile("ldmatrix.sync.aligned.m8n8.x2.shared.b16 {%0,%1}, [%2];"
        : "=r"(r[0]), "=r"(r[1]) : "r"(addr));
}
__device__ __forceinline__ void mma16816(float* d, const uint32_t* a, const uint32_t* b) {
    asm volatile("mma.sync.aligned.m16n8k16.row.col.f32.bf16.bf16.f32 "
        "{%0,%1,%2,%3}, {%4,%5,%6,%7}, {%8,%9}, {%0,%1,%2,%3};"
        : "+f"(d[0]), "+f"(d[1]), "+f"(d[2]), "+f"(d[3])
        : "r"(a[0]), "r"(a[1]), "r"(a[2]), "r"(a[3]), "r"(b[0]), "r"(b[1]));
}
__device__ __forceinline__ void cpasync16(uint32_t dst, const void* src) {
    asm volatile("cp.async.cg.shared.global [%0], [%1], 16;" :: "r"(dst), "l"(src));
}
#define CP_COMMIT() asm volatile("cp.async.commit_group;" ::: "memory")
#define CP_WAIT(n)  asm volatile("cp.async.wait_group %0;" :: "n"(n) : "memory")

// ======================= device scratch ===================================
__device__ __align__(16) unsigned short g_zb[(size_t)NN * DD];  // bf16 z
__device__ __align__(16) unsigned short g_eb[(size_t)KK * DD];  // bf16 e
__device__ float               g_sz[NN];
__device__ float               g_se[KK];
__device__ unsigned long long  g_best[NN];      // (distbits<<32)|k
__device__ int                 g_idx[NN];
__device__ int                 g_ncand;
__device__ int2                g_cand[CAP];
__device__ double              g_losssum;

// ======================= init =============================================
__global__ void vq_init()
{
    int i = blockIdx.x * 256 + threadIdx.x;
    if (i < NN) g_best[i] = 0xFFFFFFFFFFFFFFFFull;
    if (i == 0) { g_losssum = 0.0; g_ncand = 0; }
}

// ======================= fp32 -> bf16 converts ============================
__global__ void vq_tobf16_z(const float* __restrict__ x)
{
    int i = blockIdx.x * 256 + threadIdx.x;
    if (i >= NN * DD / 4) return;
    float4 v = ((const float4*)x)[i];
    ((__nv_bfloat162*)g_zb)[2 * i + 0] = __floats2bfloat162_rn(v.x, v.y);
    ((__nv_bfloat162*)g_zb)[2 * i + 1] = __floats2bfloat162_rn(v.z, v.w);
}
__global__ void vq_tobf16_e(const float* __restrict__ x)
{
    int i = blockIdx.x * 256 + threadIdx.x;
    if (i >= KK * DD / 4) return;
    float4 v = ((const float4*)x)[i];
    ((__nv_bfloat162*)g_eb)[2 * i + 0] = __floats2bfloat162_rn(v.x, v.y);
    ((__nv_bfloat162*)g_eb)[2 * i + 1] = __floats2bfloat162_rn(v.z, v.w);
}

// ======================= row squared-norms ================================
__global__ void vq_rowsq(const float* __restrict__ x, int rows, int which)
{
    int row  = blockIdx.x * 8 + (threadIdx.x >> 5);
    int lane = threadIdx.x & 31;
    if (row >= rows) return;
    const float4* xr = (const float4*)(x + (size_t)row * DD);
    double s = 0.0;
    #pragma unroll
    for (int i = 0; i < 4; i++) {
        float4 v = xr[lane + 32 * i];
        s += (double)v.x * v.x + (double)v.y * v.y
           + (double)v.z * v.z + (double)v.w * v.w;
    }
    #pragma unroll
    for (int o = 16; o >= 1; o >>= 1)
        s += __shfl_down_sync(0xffffffffu, s, o);
    if (lane == 0) {
        float r = (float)s;
        if (which == 0) g_sz[row] = r; else g_se[row] = r;
    }
}

// ======================= HMMA GEMM + candidate scan =======================
// CTA: 256 thr = 8 warps in 2(M) x 4(N) grid. Tile 128 rows x 128 codebook
// entries, full D=512 depth. A (z tile, 128x512 bf16 = 128 KB) resident in
// smem, XOR-swizzled for conflict-free ldmatrix. B (e) streamed in
// 64-deep chunks, double-buffered via cp.async, row stride padded to 144 B.
// acc = z . e^T (fp32). Epilogue per 128-entry tile: per-row running MAX of
// dot (min dist = -2 max dot), then scan acc >= runmax - EPS2 -> candidates.
#define SM_A   0
#define SM_B0  131072
#define SM_B1  (131072 + 18432)
#define SM_RT  (131072 + 2 * 18432)         /* rowtile: 128*4 floats   */
#define SM_RM  (SM_RT + 2048)               /* running rowmax: 128 f   */
#define SMEMSZ (SM_RM + 512)

__global__ void __launch_bounds__(256, 1) vq_mma()
{
    extern __shared__ char smem[];
    const int tid    = threadIdx.x;
    const int wid    = tid >> 5, lane = tid & 31;
    const int warp_m = wid >> 2, warp_n = wid & 3;
    const int m0     = blockIdx.x * 128;
    const uint32_t sb = smem_to_u32(smem);
    float* rowtile  = (float*)(smem + SM_RT);
    float* s_rowmax = (float*)(smem + SM_RM);

    // ---- load z tile resident (swizzle: unit c ^= row&7) ----
    for (int i = tid; i < 128 * 64; i += 256) {
        int r = i >> 6, c = i & 63;
        uint4 v = *((const uint4*)(g_zb + (size_t)(m0 + r) * DD) + c);
        *(uint4*)(smem + SM_A + r * 1024 + ((c ^ (r & 7)) << 4)) = v;
    }
    if (tid < 128) s_rowmax[tid] = -3.4e38f;
    __syncthreads();

    // ---- per-thread ldmatrix address precompute ----
    const int mat = lane >> 3, rq = lane & 7;
    uint32_t a_row[4], a_x[4];
    #pragma unroll
    for (int mt = 0; mt < 4; mt++) {
        int rg = warp_m * 64 + mt * 16 + (mat & 1) * 8 + rq;
        a_row[mt] = sb + SM_A + rg * 1024;
        a_x[mt]   = (uint32_t)((rg & 7) << 4);
    }
    const uint32_t a_hi = (uint32_t)((mat >> 1) << 4);
    const int tb = lane & 15;
    const int matb = tb >> 3, rbq = tb & 7;
    uint32_t b_off[4];
    #pragma unroll
    for (int n4 = 0; n4 < 4; n4++)
        b_off[n4] = (uint32_t)((warp_n * 32 + n4 * 8 + rbq) * 144 + (matb << 4));

    const int myr = tid >> 3, myc = tid & 7;  // cp.async lane mapping

    #pragma unroll 1
    for (int nt = 0; nt < 64; nt++) {
        const unsigned short* ebase = g_eb + (size_t)(nt * 128) * DD;

        // prefetch chunk 0 -> buf0
        #pragma unroll
        for (int p = 0; p < 4; p++) {
            int r = myr + p * 32;
            cpasync16(sb + SM_B0 + r * 144 + (myc << 4),
                      ebase + (size_t)r * DD + myc * 8);
        }
        CP_COMMIT();

        float acc[4][4][4];
        #pragma unroll
        for (int mt = 0; mt < 4; mt++)
            #pragma unroll
            for (int n4 = 0; n4 < 4; n4++)
                #pragma unroll
                for (int q = 0; q < 4; q++) acc[mt][n4][q] = 0.0f;

        #pragma unroll 1
        for (int ch = 0; ch < 8; ch++) {
            const uint32_t bufb = sb + ((ch & 1) ? SM_B1 : SM_B0);
            if (ch < 7) {
                const uint32_t nbuf = sb + (((ch + 1) & 1) ? SM_B1 : SM_B0);
                const int d0 = (ch + 1) * 64;
                #pragma unroll
                for (int p = 0; p < 4; p++) {
                    int r = myr + p * 32;
                    cpasync16(nbuf + r * 144 + (myc << 4),
                              ebase + (size_t)r * DD + d0 + myc * 8);
                }
                CP_COMMIT();
                CP_WAIT(1);
            } else {
                CP_WAIT(0);
            }
            __syncthreads();

            #pragma unroll
            for (int ks = 0; ks < 4; ks++) {
                const uint32_t au = (uint32_t)((ch * 8 + ks * 2) << 4);
                uint32_t afrag[4][4], bfrag[4][2];
                #pragma unroll
                for (int mt = 0; mt < 4; mt++)
                    ldsm_x4(afrag[mt], a_row[mt] + ((au + a_hi) ^ a_x[mt]));
                #pragma unroll
                for (int n4 = 0; n4 < 4; n4++)
                    ldsm_x2(bfrag[n4], bufb + b_off[n4] + (ks << 5));
                #pragma unroll
                for (int mt = 0; mt < 4; mt++)
                    #pragma unroll
                    for (int n4 = 0; n4 < 4; n4++)
                        mma16816(acc[mt][n4], afrag[mt], bfrag[n4]);
            }
            __syncthreads();
        }

        // ---- epilogue: per-row max, merge, scan candidates ----
        float vmax[4][2];
        #pragma unroll
        for (int mt = 0; mt < 4; mt++)
            #pragma unroll
            for (int h = 0; h < 2; h++) {
                float m = -3.4e38f;
                #pragma unroll
                for (int n4 = 0; n4 < 4; n4++)
                    m = fmaxf(m, fmaxf(acc[mt][n4][2 * h], acc[mt][n4][2 * h + 1]));
                m = fmaxf(m, __shfl_xor_sync(0xffffffffu, m, 1));
                m = fmaxf(m, __shfl_xor_sync(0xffffffffu, m, 2));
                vmax[mt][h] = m;
            }
        if ((lane & 3) == 0) {
            #pragma unroll
            for (int mt = 0; mt < 4; mt++)
                #pragma unroll
                for (int h = 0; h < 2; h++) {
                    int rl = warp_m * 64 + mt * 16 + (lane >> 2) + 8 * h;
                    rowtile[rl * 4 + warp_n] = vmax[mt][h];
                }
        }
        __syncthreads();
        if (tid < 128) {
            float m = fmaxf(fmaxf(rowtile[tid * 4 + 0], rowtile[tid * 4 + 1]),
                            fmaxf(rowtile[tid * 4 + 2], rowtile[tid * 4 + 3]));
            s_rowmax[tid] = fmaxf(s_rowmax[tid], m);
        }
        __syncthreads();
        #pragma unroll
        for (int mt = 0; mt < 4; mt++)
            #pragma unroll
            for (int h = 0; h < 2; h++) {
                int rl = warp_m * 64 + mt * 16 + (lane >> 2) + 8 * h;
                float thr = s_rowmax[rl] - EPS2;
                #pragma unroll
                for (int n4 = 0; n4 < 4; n4++)
                    #pragma unroll
                    for (int j = 0; j < 2; j++) {
                        float v = acc[mt][n4][2 * h + j];
                        if (v >= thr) {
                            int col = nt * 128 + warp_n * 32 + n4 * 8 + 2 * (lane & 3) + j;
                            int pos = atomicAdd(&g_ncand, 1);
                            if (pos < CAP) g_cand[pos] = make_int2(m0 + rl, col);
                        }
                    }
            }
        __syncthreads();
    }
}

// ======================= exact rescue (reference-rounded) =================
__global__ void vq_recheck(const float* __restrict__ z, const float* __restrict__ e)
{
    int i = blockIdx.x * 256 + threadIdx.x;
    int n = g_ncand; if (n > CAP) n = CAP;
    if (i >= n) return;
    int2 cd = g_cand[i];
    int row = cd.x, k = cd.y;
    const float4* zr = (const float4*)(z + (size_t)row * DD);
    const float4* er = (const float4*)(e + (size_t)k * DD);
    float acc = 0.0f;
    #pragma unroll 8
    for (int j = 0; j < DD / 4; j++) {
        float4 a = zr[j], b = er[j];
        acc = fmaf(a.x, b.x, acc);
        acc = fmaf(a.y, b.y, acc);
        acc = fmaf(a.z, b.z, acc);
        acc = fmaf(a.w, b.w, acc);
    }
    float A = g_sz[row] + g_se[k];
    float dist = A - 2.0f * acc;
    unsigned long long key =
        (((unsigned long long)__float_as_uint(dist)) << 32) | (unsigned)k;
    atomicMin(&g_best[row], key);
}

// ======================= gather + STE + loss ==============================
__global__ void vq_gather(const float* __restrict__ z, const float* __restrict__ e,
                          float* __restrict__ out, int write_q)
{
    __shared__ double warpsum[4];
    int row = blockIdx.x;
    int t   = threadIdx.x;                    // 0..127
    int k   = (int)(g_best[row] & 0xffffffffull);
    if (t == 0) g_idx[row] = k;
    float4 q  = ((const float4*)(e + (size_t)k   * DD))[t];
    float4 zz = ((const float4*)(z + (size_t)row * DD))[t];
    float d0 = q.x - zz.x, d1 = q.y - zz.y, d2 = q.z - zz.z, d3 = q.w - zz.w;
    if (write_q) {
        float4 o = make_float4(zz.x + d0, zz.y + d1, zz.z + d2, zz.w + d3);
        ((float4*)out)[(size_t)row * (DD / 4) + t] = o;
    }
    float s0 = d0 * d0, s1 = d1 * d1, s2 = d2 * d2, s3 = d3 * d3;
    double s = (double)s0 + (double)s1 + (double)s2 + (double)s3;
    #pragma unroll
    for (int o = 16; o >= 1; o >>= 1)
        s += __shfl_down_sync(0xffffffffu, s, o);
    if ((t & 31) == 0) warpsum[t >> 5] = s;
    __syncthreads();
    if (t == 0) {
        double tot = warpsum[0] + warpsum[1] + warpsum[2] + warpsum[3];
        atomicAdd(&g_losssum, tot);
    }
}

// ======================= tail / alt outputs ===============================
__global__ void vq_tail(float* __restrict__ out, long long out_size,
                        long long loss_pos, long long idx_base)
{
    long long pos = (long long)NN * DD + (long long)blockIdx.x * 256 + threadIdx.x;
    if (pos >= out_size) return;
    if (pos == loss_pos) {
        float m = (float)(g_losssum / (double)((long long)NN * DD));
        out[pos] = m + 0.25f * m;
    } else if (idx_base >= 0 && pos >= idx_base && pos < idx_base + NN) {
        out[pos] = (float)g_idx[pos - idx_base];
    } else {
        out[pos] = 0.0f;
    }
}
__global__ void vq_idx_int(int* __restrict__ out)
{
    int i = blockIdx.x * 256 + threadIdx.x;
    if (i < NN) out[i] = g_idx[i];
}
__global__ void vq_loss_only(float* __restrict__ out)
{
    float m = (float)(g_losssum / (double)((long long)NN * DD));
    out[0] = m + 0.25f * m;
}

// ======================= launch ===========================================
extern "C" void kernel_launch(void* const* d_in, const int* in_sizes, int n_in,
                              void* d_out, int out_size)
{
    const float* z = nullptr;
    const float* e = nullptr;
    for (int i = 0; i < n_in; i++) {
        if      (in_sizes[i] == NN * DD) z = (const float*)d_in[i];
        else if (in_sizes[i] == KK * DD) e = (const float*)d_in[i];
    }
    if (!z) z = (const float*)d_in[0];
    if (!e) e = (const float*)d_in[1];

    cudaFuncSetAttribute(vq_mma, cudaFuncAttributeMaxDynamicSharedMemorySize, SMEMSZ);

    vq_init<<<NN / 256, 256>>>();
    vq_tobf16_z<<<(NN * DD / 4) / 256, 256>>>(z);
    vq_tobf16_e<<<(KK * DD / 4) / 256, 256>>>(e);
    vq_rowsq<<<NN / 8, 256>>>(z, NN, 0);
    vq_rowsq<<<KK / 8, 256>>>(e, KK, 1);
    vq_mma<<<NN / 128, 256, SMEMSZ>>>();
    vq_recheck<<<CAP / 256, 256>>>(z, e);

    const long long QD = (long long)NN * DD;   // 16777216
    long long OS = (long long)out_size;

    if (OS >= QD) {
        vq_gather<<<NN, 128>>>(z, e, (float*)d_out, 1);
        long long rem = OS - QD;
        if (rem > 0) {
            long long loss_pos = -1, idx_base = -1;
            if (rem >= 1 + (long long)NN) { loss_pos = QD; idx_base = QD + 1; }
            else if (rem == (long long)NN) { idx_base = QD; }
            else { loss_pos = QD; }
            int blocks = (int)((rem + 255) / 256);
            vq_tail<<<blocks, 256>>>((float*)d_out, OS, loss_pos, idx_base);
        }
    } else if (OS == NN) {
        vq_gather<<<NN, 128>>>(z, e, nullptr, 0);
        vq_idx_int<<<NN / 256, 256>>>((int*)d_out);
    } else if (OS == 1) {
        vq_gather<<<NN, 128>>>(z, e, nullptr, 0);
        vq_loss_only<<<1, 1>>>((float*)d_out);
    } else {
        vq_gather<<<NN, 128>>>(z, e, nullptr, 0);
    }
}